// round 16
// baseline (speedup 1.0000x reference)
#include <cuda_runtime.h>
#include <cstdint>

#define BB 4096
#define NN 8192
#define DD 512
#define RR 4
#define NBLK (NN / 4)   // 2048 blocks of 4 warps for the logits kernel

__device__ float g_rnorm[NN];
__device__ float g_partial[NBLK];
__device__ unsigned int g_ticket;   // zero-init at load; reset by block 0 each run

__device__ __forceinline__ const float4* row_ptr4(const float* zi, const float* zj, int r) {
    const float* p = (r < BB) ? (zi + (size_t)r * DD) : (zj + (size_t)(r - BB) * DD);
    return reinterpret_cast<const float4*>(p);
}

// Kernel 1: per-row inverse norms (byte-identical to the round-5 version,
// measured 7.2us). Also warms L2 with the full 16MB embedding set, which is
// what makes the logits gathers fast.
__global__ void norms_kernel(const float* __restrict__ zi, const float* __restrict__ zj) {
    int warp = (blockIdx.x * blockDim.x + threadIdx.x) >> 5;
    int lane = threadIdx.x & 31;
    if (warp >= NN) return;
    const float4* p = row_ptr4(zi, zj, warp);
    float s = 0.0f;
#pragma unroll
    for (int k = 0; k < 4; k++) {
        float4 v = p[lane + 32 * k];
        s += v.x * v.x + v.y * v.y + v.z * v.z + v.w * v.w;
    }
#pragma unroll
    for (int o = 16; o; o >>= 1) s += __shfl_xor_sync(0xFFFFFFFFu, s, o);
    if (lane == 0) g_rnorm[warp] = 1.0f / fmaxf(sqrtf(s), 1e-8f);
}

// Kernel 2: round-5 logits body (measured 5.75us: per-partner loads consumed
// immediately -> schedule-robust codegen, L2-warm gathers) + the round-13
// free tail (st.cg partial, fire-and-forget release ticket, block 0 reduces
// the 2048 partials in fixed order and resets the ticket for graph replay).
__global__ void logits_kernel(const float* __restrict__ zi, const float* __restrict__ zj,
                              const int* __restrict__ neg_idx, float* __restrict__ out) {
    __shared__ float s_nll[4];
    __shared__ float s_ws[4];

    int warp = threadIdx.x >> 5;
    int lane = threadIdx.x & 31;
    int row  = blockIdx.x * 4 + warp;

    const float4* pi = row_ptr4(zi, zj, row);
    float4 x[4];
#pragma unroll
    for (int k = 0; k < 4; k++) x[k] = pi[lane + 32 * k];

    int part[5];
    part[0] = (row + BB) & (NN - 1);
#pragma unroll
    for (int r = 0; r < RR; r++) {
        int v = neg_idx[row * RR + r];
        part[r + 1] = v + (v >= row ? 1 : 0);
    }

    float dots[5];
#pragma unroll
    for (int p = 0; p < 5; p++) {
        const float4* pj = row_ptr4(zi, zj, part[p]);
        float4 y0 = pj[lane];
        float4 y1 = pj[lane + 32];
        float4 y2 = pj[lane + 64];
        float4 y3 = pj[lane + 96];
        float acc = 0.0f;
        acc += x[0].x * y0.x + x[0].y * y0.y + x[0].z * y0.z + x[0].w * y0.w;
        acc += x[1].x * y1.x + x[1].y * y1.y + x[1].z * y1.z + x[1].w * y1.w;
        acc += x[2].x * y2.x + x[2].y * y2.y + x[2].z * y2.z + x[2].w * y2.w;
        acc += x[3].x * y3.x + x[3].y * y3.y + x[3].z * y3.z + x[3].w * y3.w;
        dots[p] = acc;
    }
#pragma unroll
    for (int p = 0; p < 5; p++) {
#pragma unroll
        for (int o = 16; o; o >>= 1) dots[p] += __shfl_xor_sync(0xFFFFFFFFu, dots[p], o);
    }

    if (lane == 0) {
        const float invT = 1.0f / (0.5f + 1e-8f);
        float si = g_rnorm[row];
        float l[5];
#pragma unroll
        for (int p = 0; p < 5; p++) l[p] = dots[p] * si * g_rnorm[part[p]] * invT;
        float m = l[0];
#pragma unroll
        for (int p = 1; p < 5; p++) m = fmaxf(m, l[p]);
        float se = 0.0f;
#pragma unroll
        for (int p = 0; p < 5; p++) se += expf(l[p] - m);
        s_nll[warp] = m + logf(se) - l[0];
    }
    __syncthreads();

    // ---- free tail: block partial to L2 + fire-and-forget release ticket ----
    if (threadIdx.x == 0) {
        float partial = s_nll[0] + s_nll[1] + s_nll[2] + s_nll[3];
        asm volatile("st.global.cg.f32 [%0], %1;"
                     :: "l"(&g_partial[blockIdx.x]), "f"(partial) : "memory");
        asm volatile("red.release.gpu.global.add.u32 [%0], 1;"
                     :: "l"(&g_ticket) : "memory");
    }

    // ---- block 0 = designated reducer (deterministic, fixed order) ----
    if (blockIdx.x == 0) {
        if (threadIdx.x == 0) {
            unsigned int v;
            do {
                __nanosleep(64);
                asm volatile("ld.acquire.gpu.global.u32 %0, [%1];"
                             : "=r"(v) : "l"(&g_ticket));
            } while (v < (unsigned int)NBLK);
        }
        __syncthreads();

        float s = 0.0f;
#pragma unroll
        for (int k = 0; k < NBLK / 128; k++) {
            float v;
            asm volatile("ld.global.cg.f32 %0, [%1];"
                         : "=f"(v) : "l"(&g_partial[threadIdx.x + k * 128]));
            s += v;
        }
#pragma unroll
        for (int o = 16; o; o >>= 1) s += __shfl_xor_sync(0xFFFFFFFFu, s, o);
        if (lane == 0) s_ws[warp] = s;
        __syncthreads();
        if (threadIdx.x == 0) {
            float tot = s_ws[0] + s_ws[1] + s_ws[2] + s_ws[3];
            out[0] = tot * (1.0f / (float)NN);
            g_ticket = 0u;   // all blocks arrived; safe reset for next replay
        }
    }
}

extern "C" void kernel_launch(void* const* d_in, const int* in_sizes, int n_in,
                              void* d_out, int out_size) {
    const float* zi      = (const float*)d_in[0];
    const float* zj      = (const float*)d_in[1];
    const int*   neg_idx = (const int*)d_in[2];
    float* out = (float*)d_out;

    norms_kernel<<<NN / 4, 128>>>(zi, zj);
    logits_kernel<<<NBLK, 128>>>(zi, zj, neg_idx, out);
}